// round 6
// baseline (speedup 1.0000x reference)
#include <cuda_runtime.h>
#include <cuda_fp16.h>
#include <cstdint>

// Problem constants
#define B_  64
#define L_  1024
#define H_  128

// ---------------------------------------------------------------------------
// Scratch (allocation-free rule: __device__ globals)
// fp16 1-term scheme: ah = fp16(body*w3); ph = fp16(pun)
// s_cross ≈ ah·ph  (dropped al·p and ah·pl, each ~2^-11 relative;
// measured calibration: 2-term = 1.24e-4 -> 1-term ≈ sqrt(2)·1.24e-4 ≈ 1.8e-4)
// ---------------------------------------------------------------------------
__device__ __align__(16) __half g_Ah[(size_t)B_*L_*H_];
__device__ __align__(16) __half g_Ph[(size_t)B_*L_*H_];
__device__ float g_sbody[B_*L_];
__device__ float g_spun [B_*L_];

// ---------------------------------------------------------------------------
// Helpers (base-arch only: NO tcgen05 — ptxas target is sm_103, not sm_103a)
// ---------------------------------------------------------------------------
__device__ __forceinline__ uint32_t smem_u32(const void* p) {
    uint32_t a;
    asm("{ .reg .u64 t; cvta.to.shared.u64 t, %1; cvt.u32.u64 %0, t; }" : "=r"(a) : "l"(p));
    return a;
}

__device__ __forceinline__ void ldsm_x4(uint32_t* r, uint32_t addr) {
    asm volatile("ldmatrix.sync.aligned.m8n8.x4.shared.b16 {%0,%1,%2,%3}, [%4];"
        : "=r"(r[0]), "=r"(r[1]), "=r"(r[2]), "=r"(r[3]) : "r"(addr));
}

// D += A * B  (m16n8k16, fp16 in, f32 accum)
__device__ __forceinline__ void mma_f16(float* d, const uint32_t* a, const uint32_t* b) {
    asm volatile(
        "mma.sync.aligned.m16n8k16.row.col.f32.f16.f16.f32 "
        "{%0,%1,%2,%3}, {%4,%5,%6,%7}, {%8,%9}, {%0,%1,%2,%3};"
        : "+f"(d[0]), "+f"(d[1]), "+f"(d[2]), "+f"(d[3])
        : "r"(a[0]), "r"(a[1]), "r"(a[2]), "r"(a[3]), "r"(b[0]), "r"(b[1]));
}

__device__ __forceinline__ void cp_async16(uint32_t dst, const void* src) {
    asm volatile("cp.async.cg.shared.global [%0], [%1], 16;" :: "r"(dst), "l"(src));
}
#define CP_COMMIT() asm volatile("cp.async.commit_group;" ::: "memory")
#define CP_WAIT(n)  asm volatile("cp.async.wait_group %0;" :: "n"(n) : "memory")

// ---------------------------------------------------------------------------
// Kernel 1: preprocess — ah = fp16(body*w3); ph = fp16(pun); rank-1 dots.
// One warp per row (float4 per lane).
// ---------------------------------------------------------------------------
__device__ __forceinline__ uint32_t pack_h2(float x, float y) {
    __half2 v(__float2half(x), __float2half(y));
    return *reinterpret_cast<uint32_t*>(&v);
}

__global__ void __launch_bounds__(256) prep_kernel(const float* __restrict__ body,
                                                   const float* __restrict__ pun,
                                                   const float* __restrict__ w_u) {
    const int warp = threadIdx.x >> 5, lane = threadIdx.x & 31;
    const int r = blockIdx.x * 8 + warp;
    const int d4 = lane * 4;

    const float4 w1 = *reinterpret_cast<const float4*>(w_u + d4);
    const float4 w2 = *reinterpret_cast<const float4*>(w_u + H_ + d4);
    const float4 w3 = *reinterpret_cast<const float4*>(w_u + 2 * H_ + d4);

    const size_t idx = (size_t)r * H_ + d4;
    const float4 bv = *reinterpret_cast<const float4*>(body + idx);
    const float4 pv = *reinterpret_cast<const float4*>(pun + idx);

    // A = body*w3 -> fp16
    float a0 = bv.x * w3.x, a1 = bv.y * w3.y, a2 = bv.z * w3.z, a3 = bv.w * w3.w;
    *reinterpret_cast<uint2*>(g_Ah + idx) =
        make_uint2(pack_h2(a0, a1), pack_h2(a2, a3));

    // P = pun -> fp16
    *reinterpret_cast<uint2*>(g_Ph + idx) =
        make_uint2(pack_h2(pv.x, pv.y), pack_h2(pv.z, pv.w));

    // rank-1 dot products
    float sb = bv.x * w1.x + bv.y * w1.y + bv.z * w1.z + bv.w * w1.w;
    float sp = pv.x * w2.x + pv.y * w2.y + pv.z * w2.z + pv.w * w2.w;
    #pragma unroll
    for (int o = 16; o > 0; o >>= 1) {
        sb += __shfl_down_sync(0xFFFFFFFFu, sb, o);
        sp += __shfl_down_sync(0xFFFFFFFFu, sp, o);
    }
    if (lane == 0) { g_sbody[r] = sb; g_spun[r] = sp; }
}

// ---------------------------------------------------------------------------
// Kernel 2: mma.sync fp16 1-term batched GEMM
//   CTA tile 128x128; whole K=128 resident in smem (2 stages of KC=64).
//   2 __syncthreads total; barrier-free k-loops for ptxas pipelining.
// smem: sbody(512B) spun(512B) then 2 stages x {Ah,Ph} slabs of 16 KB
//   slab = 128 rows x 128B (64 fp16); swizzle phys_chunk16 = ch ^ (row&7)
// ---------------------------------------------------------------------------
static constexpr int KC = 64;
static constexpr int OFF_SB  = 0;
static constexpr int OFF_SP  = 512;
static constexpr int OFF_BUF = 1024;
static constexpr int SLAB    = 16384;      // one 128x64 fp16 slab
static constexpr int STAGE   = 2 * SLAB;   // 32 KB
static constexpr int SMEM_TOTAL = OFF_BUF + 2 * STAGE;  // 66560 B -> occ 3

__device__ __forceinline__ void load_slab(uint32_t dst, const __half* __restrict__ g,
                                          int row0, int kk, int tid) {
    #pragma unroll
    for (int l = 0; l < 4; l++) {
        const int cidx = tid + l * 256;     // 0..1023
        const int row  = cidx >> 3;
        const int ch   = cidx & 7;
        const uint32_t off = (uint32_t)(row * 128 + ((ch ^ (row & 7)) << 4));
        cp_async16(dst + off, g + (size_t)(row0 + row) * H_ + kk + ch * 8);
    }
}

__device__ __forceinline__ void load_stage(uint32_t buf, size_t base, int i0, int j0,
                                           int kk, int tid) {
    load_slab(buf,        g_Ah + base, i0, kk, tid);
    load_slab(buf + SLAB, g_Ph + base, j0, kk, tid);
}

__global__ void __launch_bounds__(256, 3)
gemm_kernel(float* __restrict__ out) {
    extern __shared__ char smem[];
    const uint32_t sbase = smem_u32(smem);
    const int tid  = threadIdx.x;
    const int lane = tid & 31;
    const int warp = tid >> 5;
    const int m_base = (warp & 1) * 64;   // 2 warps over M
    const int n_base = (warp >> 1) * 32;  // 4 warps over N

    const int b  = blockIdx.z;
    const int i0 = blockIdx.y * 128;
    const int j0 = blockIdx.x * 128;
    const size_t base = (size_t)b * L_ * H_;

    // prologue: both K-chunks in flight immediately (max MLP)
    load_stage(sbase + OFF_BUF,         base, i0, j0, 0,  tid); CP_COMMIT();
    load_stage(sbase + OFF_BUF + STAGE, base, i0, j0, KC, tid); CP_COMMIT();

    // rank-1 vector slices (regular loads, overlap with cp.async)
    if (tid < 128)       ((float*)(smem + OFF_SB))[tid]       = g_sbody[b * L_ + i0 + tid];
    else                 ((float*)(smem + OFF_SP))[tid - 128] = g_spun [b * L_ + j0 + (tid - 128)];

    float acc[4][4][4];
    #pragma unroll
    for (int mi = 0; mi < 4; mi++)
        #pragma unroll
        for (int ni = 0; ni < 4; ni++)
            #pragma unroll
            for (int k = 0; k < 4; k++) acc[mi][ni][k] = 0.f;

    // fragment addressing (constant per thread)
    const int a_row  = (lane & 7) + ((lane >> 3) & 1) * 8;
    const int a_half = lane >> 4;
    const int b_row  = (lane & 7) + (lane >> 4) * 8;
    const int b_half = (lane >> 3) & 1;

    #pragma unroll
    for (int c = 0; c < 2; c++) {
        if (c == 0) CP_WAIT(1); else CP_WAIT(0);
        __syncthreads();   // stage c visible to all warps

        const uint32_t buf = sbase + OFF_BUF + c * STAGE;
        #pragma unroll
        for (int ks = 0; ks < KC / 16; ks++) {
            // --- B fragments via ldmatrix.x4: 2 n-tiles per load ---
            uint32_t bH[4][2];
            {
                const int chunk = ks * 2 + b_half;
                #pragma unroll
                for (int np = 0; np < 2; np++) {
                    const int nrow = n_base + np * 16 + b_row;
                    const uint32_t off = (uint32_t)(nrow * 128 + ((chunk ^ (nrow & 7)) << 4));
                    uint32_t r[4];
                    ldsm_x4(r, buf + SLAB + off);          // Ph
                    bH[np*2][0] = r[0]; bH[np*2][1] = r[1];
                    bH[np*2+1][0] = r[2]; bH[np*2+1][1] = r[3];
                }
            }
            // --- A fragments + MMAs (1 per mi,ni) ---
            const int achunk = ks * 2 + a_half;
            #pragma unroll
            for (int mi = 0; mi < 4; mi++) {
                uint32_t aH[4];
                const int arow = m_base + mi * 16 + a_row;
                const uint32_t off = (uint32_t)(arow * 128 + ((achunk ^ (arow & 7)) << 4));
                ldsm_x4(aH, buf + off);                    // Ah
                #pragma unroll
                for (int ni = 0; ni < 4; ni++) {
                    mma_f16(acc[mi][ni], aH, bH[ni]);      // ah*ph
                }
            }
        }
    }

    // --- epilogue: acc + sbody[row] + spun[col] -> gmem, streaming stores ---
    const float* sbV = (const float*)(smem + OFF_SB);
    const float* spV = (const float*)(smem + OFF_SP);
    const int r4 = lane >> 2;
    const int c2 = (lane & 3) << 1;
    float* outB = out + (size_t)b * L_ * L_;

    #pragma unroll
    for (int mi = 0; mi < 4; mi++) {
        const float sb0 = sbV[m_base + mi * 16 + r4];
        const float sb1 = sbV[m_base + mi * 16 + 8 + r4];
        const int row0 = i0 + m_base + mi * 16 + r4;
        #pragma unroll
        for (int ni = 0; ni < 4; ni++) {
            const int col = j0 + n_base + ni * 8 + c2;
            const float sp0 = spV[n_base + ni * 8 + c2];
            const float sp1 = spV[n_base + ni * 8 + c2 + 1];
            float2 v0 = make_float2(acc[mi][ni][0] + sb0 + sp0,
                                    acc[mi][ni][1] + sb0 + sp1);
            float2 v1 = make_float2(acc[mi][ni][2] + sb1 + sp0,
                                    acc[mi][ni][3] + sb1 + sp1);
            __stcs(reinterpret_cast<float2*>(outB + (size_t)row0 * L_ + col), v0);
            __stcs(reinterpret_cast<float2*>(outB + (size_t)(row0 + 8) * L_ + col), v1);
        }
    }
}

// ---------------------------------------------------------------------------
// Launch
// ---------------------------------------------------------------------------
extern "C" void kernel_launch(void* const* d_in, const int* in_sizes, int n_in,
                              void* d_out, int out_size) {
    const float* body = (const float*)d_in[n_in - 3];
    const float* pun  = (const float*)d_in[n_in - 2];
    const float* w_u  = (const float*)d_in[n_in - 1];
    float* out = (float*)d_out;

    prep_kernel<<<(B_ * L_) / 8, 256>>>(body, pun, w_u);

    static bool attr_set = false;
    if (!attr_set) {
        cudaFuncSetAttribute(gemm_kernel, cudaFuncAttributeMaxDynamicSharedMemorySize, SMEM_TOTAL);
        attr_set = true;
    }
    gemm_kernel<<<dim3(8, 8, B_), 256, SMEM_TOTAL>>>(out);
}

// round 7
// speedup vs baseline: 1.2518x; 1.2518x over previous
#include <cuda_runtime.h>
#include <cuda_fp16.h>
#include <cstdint>

// Problem constants
#define B_  64
#define L_  1024
#define H_  128

// ---------------------------------------------------------------------------
// Scratch (allocation-free rule: __device__ globals)
// fp16 1-term scheme: ah = fp16(body*w3); ph = fp16(pun); s_cross ≈ ah·ph
// (measured rel_err 1.75e-4, deterministic inputs)
// ---------------------------------------------------------------------------
__device__ __align__(16) __half g_Ah[(size_t)B_*L_*H_];
__device__ __align__(16) __half g_Ph[(size_t)B_*L_*H_];
__device__ float g_sbody[B_*L_];
__device__ float g_spun [B_*L_];

// ---------------------------------------------------------------------------
// Helpers (base-arch only: NO tcgen05 — ptxas target is sm_103, not sm_103a)
// ---------------------------------------------------------------------------
__device__ __forceinline__ uint32_t smem_u32(const void* p) {
    uint32_t a;
    asm("{ .reg .u64 t; cvta.to.shared.u64 t, %1; cvt.u32.u64 %0, t; }" : "=r"(a) : "l"(p));
    return a;
}

__device__ __forceinline__ void ldsm_x4(uint32_t* r, uint32_t addr) {
    asm volatile("ldmatrix.sync.aligned.m8n8.x4.shared.b16 {%0,%1,%2,%3}, [%4];"
        : "=r"(r[0]), "=r"(r[1]), "=r"(r[2]), "=r"(r[3]) : "r"(addr));
}

// D += A * B  (m16n8k16, fp16 in, f32 accum)
__device__ __forceinline__ void mma_f16(float* d, const uint32_t* a, const uint32_t* b) {
    asm volatile(
        "mma.sync.aligned.m16n8k16.row.col.f32.f16.f16.f32 "
        "{%0,%1,%2,%3}, {%4,%5,%6,%7}, {%8,%9}, {%0,%1,%2,%3};"
        : "+f"(d[0]), "+f"(d[1]), "+f"(d[2]), "+f"(d[3])
        : "r"(a[0]), "r"(a[1]), "r"(a[2]), "r"(a[3]), "r"(b[0]), "r"(b[1]));
}

__device__ __forceinline__ void cp_async16(uint32_t dst, const void* src) {
    asm volatile("cp.async.cg.shared.global [%0], [%1], 16;" :: "r"(dst), "l"(src));
}
#define CP_COMMIT() asm volatile("cp.async.commit_group;" ::: "memory")
#define CP_WAIT(n)  asm volatile("cp.async.wait_group %0;" :: "n"(n) : "memory")

// ---------------------------------------------------------------------------
// Kernel 1: preprocess — ah = fp16(body*w3); ph = fp16(pun); rank-1 dots.
// ---------------------------------------------------------------------------
__device__ __forceinline__ uint32_t pack_h2(float x, float y) {
    __half2 v(__float2half(x), __float2half(y));
    return *reinterpret_cast<uint32_t*>(&v);
}

__global__ void __launch_bounds__(256) prep_kernel(const float* __restrict__ body,
                                                   const float* __restrict__ pun,
                                                   const float* __restrict__ w_u) {
    const int warp = threadIdx.x >> 5, lane = threadIdx.x & 31;
    const int r = blockIdx.x * 8 + warp;
    const int d4 = lane * 4;

    const float4 w1 = *reinterpret_cast<const float4*>(w_u + d4);
    const float4 w2 = *reinterpret_cast<const float4*>(w_u + H_ + d4);
    const float4 w3 = *reinterpret_cast<const float4*>(w_u + 2 * H_ + d4);

    const size_t idx = (size_t)r * H_ + d4;
    const float4 bv = *reinterpret_cast<const float4*>(body + idx);
    const float4 pv = *reinterpret_cast<const float4*>(pun + idx);

    float a0 = bv.x * w3.x, a1 = bv.y * w3.y, a2 = bv.z * w3.z, a3 = bv.w * w3.w;
    *reinterpret_cast<uint2*>(g_Ah + idx) =
        make_uint2(pack_h2(a0, a1), pack_h2(a2, a3));
    *reinterpret_cast<uint2*>(g_Ph + idx) =
        make_uint2(pack_h2(pv.x, pv.y), pack_h2(pv.z, pv.w));

    float sb = bv.x * w1.x + bv.y * w1.y + bv.z * w1.z + bv.w * w1.w;
    float sp = pv.x * w2.x + pv.y * w2.y + pv.z * w2.z + pv.w * w2.w;
    #pragma unroll
    for (int o = 16; o > 0; o >>= 1) {
        sb += __shfl_down_sync(0xFFFFFFFFu, sb, o);
        sp += __shfl_down_sync(0xFFFFFFFFu, sp, o);
    }
    if (lane == 0) { g_sbody[r] = sb; g_spun[r] = sp; }
}

// ---------------------------------------------------------------------------
// Kernel 2: mma.sync fp16 1-term batched GEMM
//   CTA tile 128x128; whole K=128 resident (2 stages of KC=64).
//   Epilogue: per-warp smem staging (reuses operand buffers) -> STG.128
//   with full 128B-line coverage per wavefront.
// ---------------------------------------------------------------------------
static constexpr int KC = 64;
static constexpr int OFF_SB  = 0;
static constexpr int OFF_SP  = 512;
static constexpr int OFF_BUF = 1024;
static constexpr int SLAB    = 16384;      // one 128x64 fp16 slab
static constexpr int STAGE   = 2 * SLAB;   // 32 KB
static constexpr int SMEM_TOTAL = OFF_BUF + 2 * STAGE;  // 66560 B
static constexpr int EPI_WARP = 8192;      // 64 rows x 32 f32 per-warp staging

__device__ __forceinline__ void load_slab(uint32_t dst, const __half* __restrict__ g,
                                          int row0, int kk, int tid) {
    #pragma unroll
    for (int l = 0; l < 4; l++) {
        const int cidx = tid + l * 256;     // 0..1023
        const int row  = cidx >> 3;
        const int ch   = cidx & 7;
        const uint32_t off = (uint32_t)(row * 128 + ((ch ^ (row & 7)) << 4));
        cp_async16(dst + off, g + (size_t)(row0 + row) * H_ + kk + ch * 8);
    }
}

__device__ __forceinline__ void load_stage(uint32_t buf, size_t base, int i0, int j0,
                                           int kk, int tid) {
    load_slab(buf,        g_Ah + base, i0, kk, tid);
    load_slab(buf + SLAB, g_Ph + base, j0, kk, tid);
}

// staging swizzle: 16B chunk XOR by row (conflict-free STS + LDS)
__device__ __forceinline__ uint32_t stage_off(int rowL, int colL) {
    return (uint32_t)(rowL * 128 + ((((colL >> 2) & 7) ^ (rowL & 7)) << 4)
                      + ((colL & 3) << 2));
}

__global__ void __launch_bounds__(256, 3)
gemm_kernel(float* __restrict__ out) {
    extern __shared__ char smem[];
    const uint32_t sbase = smem_u32(smem);
    const int tid  = threadIdx.x;
    const int lane = tid & 31;
    const int warp = tid >> 5;
    const int m_base = (warp & 1) * 64;   // 2 warps over M
    const int n_base = (warp >> 1) * 32;  // 4 warps over N

    const int b  = blockIdx.z;
    const int i0 = blockIdx.y * 128;
    const int j0 = blockIdx.x * 128;
    const size_t base = (size_t)b * L_ * H_;

    // prologue: both K-chunks in flight immediately
    load_stage(sbase + OFF_BUF,         base, i0, j0, 0,  tid); CP_COMMIT();
    load_stage(sbase + OFF_BUF + STAGE, base, i0, j0, KC, tid); CP_COMMIT();

    // rank-1 vector slices
    if (tid < 128)       ((float*)(smem + OFF_SB))[tid]       = g_sbody[b * L_ + i0 + tid];
    else                 ((float*)(smem + OFF_SP))[tid - 128] = g_spun [b * L_ + j0 + (tid - 128)];

    float acc[4][4][4];
    #pragma unroll
    for (int mi = 0; mi < 4; mi++)
        #pragma unroll
        for (int ni = 0; ni < 4; ni++)
            #pragma unroll
            for (int k = 0; k < 4; k++) acc[mi][ni][k] = 0.f;

    const int a_row  = (lane & 7) + ((lane >> 3) & 1) * 8;
    const int a_half = lane >> 4;
    const int b_row  = (lane & 7) + (lane >> 4) * 8;
    const int b_half = (lane >> 3) & 1;

    #pragma unroll
    for (int c = 0; c < 2; c++) {
        if (c == 0) CP_WAIT(1); else CP_WAIT(0);
        __syncthreads();

        const uint32_t buf = sbase + OFF_BUF + c * STAGE;
        #pragma unroll
        for (int ks = 0; ks < KC / 16; ks++) {
            uint32_t bH[4][2];
            {
                const int chunk = ks * 2 + b_half;
                #pragma unroll
                for (int np = 0; np < 2; np++) {
                    const int nrow = n_base + np * 16 + b_row;
                    const uint32_t off = (uint32_t)(nrow * 128 + ((chunk ^ (nrow & 7)) << 4));
                    uint32_t r[4];
                    ldsm_x4(r, buf + SLAB + off);          // Ph
                    bH[np*2][0] = r[0]; bH[np*2][1] = r[1];
                    bH[np*2+1][0] = r[2]; bH[np*2+1][1] = r[3];
                }
            }
            const int achunk = ks * 2 + a_half;
            #pragma unroll
            for (int mi = 0; mi < 4; mi++) {
                uint32_t aH[4];
                const int arow = m_base + mi * 16 + a_row;
                const uint32_t off = (uint32_t)(arow * 128 + ((achunk ^ (arow & 7)) << 4));
                ldsm_x4(aH, buf + off);                    // Ah
                #pragma unroll
                for (int ni = 0; ni < 4; ni++)
                    mma_f16(acc[mi][ni], aH, bH[ni]);
            }
        }
    }

    // --- epilogue: add rank-1 vectors, stage in smem, store full 128B lines ---
    const float* sbV = (const float*)(smem + OFF_SB);
    const float* spV = (const float*)(smem + OFF_SP);
    const int r4 = lane >> 2;
    const int c2 = (lane & 3) << 1;

    __syncthreads();   // all warps done reading operand smem before overwrite
    const uint32_t sreg = sbase + OFF_BUF + warp * EPI_WARP;

    #pragma unroll
    for (int mi = 0; mi < 4; mi++) {
        const int r0 = mi * 16 + r4;           // local row in warp tile (0..63)
        const float sb0 = sbV[m_base + r0];
        const float sb1 = sbV[m_base + r0 + 8];
        #pragma unroll
        for (int ni = 0; ni < 4; ni++) {
            const int colL = ni * 8 + c2;
            const float sp0 = spV[n_base + colL];
            const float sp1 = spV[n_base + colL + 1];
            float2 v0 = make_float2(acc[mi][ni][0] + sb0 + sp0,
                                    acc[mi][ni][1] + sb0 + sp1);
            float2 v1 = make_float2(acc[mi][ni][2] + sb1 + sp0,
                                    acc[mi][ni][3] + sb1 + sp1);
            *reinterpret_cast<float2*>(smem + (sreg - sbase) + stage_off(r0,     colL)) = v0;
            *reinterpret_cast<float2*>(smem + (sreg - sbase) + stage_off(r0 + 8, colL)) = v1;
        }
    }
    __syncwarp();

    // read back row-linear, store 128B-line-aligned float4s
    float* outB = out + (size_t)b * L_ * L_;
    const int rl_sub = lane >> 3;          // 0..3 rows per iter
    const int cl     = (lane & 7) * 4;     // 0..28 float col
    #pragma unroll
    for (int it = 0; it < 16; it++) {
        const int rowL = it * 4 + rl_sub;
        const float4 v = *reinterpret_cast<const float4*>(
            smem + (sreg - sbase) + stage_off(rowL, cl));
        __stcs(reinterpret_cast<float4*>(
            outB + (size_t)(i0 + m_base + rowL) * L_ + j0 + n_base + cl), v);
    }
}

// ---------------------------------------------------------------------------
// Launch
// ---------------------------------------------------------------------------
extern "C" void kernel_launch(void* const* d_in, const int* in_sizes, int n_in,
                              void* d_out, int out_size) {
    const float* body = (const float*)d_in[n_in - 3];
    const float* pun  = (const float*)d_in[n_in - 2];
    const float* w_u  = (const float*)d_in[n_in - 1];
    float* out = (float*)d_out;

    prep_kernel<<<(B_ * L_) / 8, 256>>>(body, pun, w_u);

    static bool attr_set = false;
    if (!attr_set) {
        cudaFuncSetAttribute(gemm_kernel, cudaFuncAttributeMaxDynamicSharedMemorySize, SMEM_TOTAL);
        attr_set = true;
    }
    gemm_kernel<<<dim3(8, 8, B_), 256, SMEM_TOTAL>>>(out);
}

// round 8
// speedup vs baseline: 1.4120x; 1.1280x over previous
#include <cuda_runtime.h>
#include <cuda_fp16.h>
#include <cuda.h>
#include <cstdint>

// Problem constants
#define B_  64
#define L_  1024
#define H_  128

// ---------------------------------------------------------------------------
// Scratch (allocation-free rule: __device__ globals)
// fp16 1-term scheme: ah = fp16(body*w3); ph = fp16(pun); s_cross ≈ ah·ph
// (measured rel_err 1.75e-4, deterministic inputs)
// ---------------------------------------------------------------------------
__device__ __align__(16) __half g_Ah[(size_t)B_*L_*H_];
__device__ __align__(16) __half g_Ph[(size_t)B_*L_*H_];
__device__ float g_sbody[B_*L_];
__device__ float g_spun [B_*L_];

// ---------------------------------------------------------------------------
// Helpers (base-arch only: NO tcgen05 — ptxas target is sm_103, not sm_103a.
// cp.async.bulk.tensor IS base sm_90+.)
// ---------------------------------------------------------------------------
__device__ __forceinline__ uint32_t smem_u32(const void* p) {
    uint32_t a;
    asm("{ .reg .u64 t; cvta.to.shared.u64 t, %1; cvt.u32.u64 %0, t; }" : "=r"(a) : "l"(p));
    return a;
}

__device__ __forceinline__ void ldsm_x4(uint32_t* r, uint32_t addr) {
    asm volatile("ldmatrix.sync.aligned.m8n8.x4.shared.b16 {%0,%1,%2,%3}, [%4];"
        : "=r"(r[0]), "=r"(r[1]), "=r"(r[2]), "=r"(r[3]) : "r"(addr));
}

// D += A * B  (m16n8k16, fp16 in, f32 accum)
__device__ __forceinline__ void mma_f16(float* d, const uint32_t* a, const uint32_t* b) {
    asm volatile(
        "mma.sync.aligned.m16n8k16.row.col.f32.f16.f16.f32 "
        "{%0,%1,%2,%3}, {%4,%5,%6,%7}, {%8,%9}, {%0,%1,%2,%3};"
        : "+f"(d[0]), "+f"(d[1]), "+f"(d[2]), "+f"(d[3])
        : "r"(a[0]), "r"(a[1]), "r"(a[2]), "r"(a[3]), "r"(b[0]), "r"(b[1]));
}

__device__ __forceinline__ void cp_async16(uint32_t dst, const void* src) {
    asm volatile("cp.async.cg.shared.global [%0], [%1], 16;" :: "r"(dst), "l"(src));
}
#define CP_COMMIT() asm volatile("cp.async.commit_group;" ::: "memory")
#define CP_WAIT(n)  asm volatile("cp.async.wait_group %0;" :: "n"(n) : "memory")

// ---------------------------------------------------------------------------
// Kernel 1: preprocess — ah = fp16(body*w3); ph = fp16(pun); rank-1 dots.
// ---------------------------------------------------------------------------
__device__ __forceinline__ uint32_t pack_h2(float x, float y) {
    __half2 v(__float2half(x), __float2half(y));
    return *reinterpret_cast<uint32_t*>(&v);
}

__global__ void __launch_bounds__(256) prep_kernel(const float* __restrict__ body,
                                                   const float* __restrict__ pun,
                                                   const float* __restrict__ w_u) {
    const int warp = threadIdx.x >> 5, lane = threadIdx.x & 31;
    const int r = blockIdx.x * 8 + warp;
    const int d4 = lane * 4;

    const float4 w1 = *reinterpret_cast<const float4*>(w_u + d4);
    const float4 w2 = *reinterpret_cast<const float4*>(w_u + H_ + d4);
    const float4 w3 = *reinterpret_cast<const float4*>(w_u + 2 * H_ + d4);

    const size_t idx = (size_t)r * H_ + d4;
    const float4 bv = *reinterpret_cast<const float4*>(body + idx);
    const float4 pv = *reinterpret_cast<const float4*>(pun + idx);

    float a0 = bv.x * w3.x, a1 = bv.y * w3.y, a2 = bv.z * w3.z, a3 = bv.w * w3.w;
    *reinterpret_cast<uint2*>(g_Ah + idx) =
        make_uint2(pack_h2(a0, a1), pack_h2(a2, a3));
    *reinterpret_cast<uint2*>(g_Ph + idx) =
        make_uint2(pack_h2(pv.x, pv.y), pack_h2(pv.z, pv.w));

    float sb = bv.x * w1.x + bv.y * w1.y + bv.z * w1.z + bv.w * w1.w;
    float sp = pv.x * w2.x + pv.y * w2.y + pv.z * w2.z + pv.w * w2.w;
    #pragma unroll
    for (int o = 16; o > 0; o >>= 1) {
        sb += __shfl_down_sync(0xFFFFFFFFu, sb, o);
        sp += __shfl_down_sync(0xFFFFFFFFu, sp, o);
    }
    if (lane == 0) { g_sbody[r] = sb; g_spun[r] = sp; }
}

// ---------------------------------------------------------------------------
// Kernel 2: mma.sync fp16 1-term batched GEMM
//   CTA tile 128x128; whole K=128 resident (2 stages of KC=64).
//   Epilogue: STS to SW128-staged f32 regions, then 4x TMA 2D tensor store
//   (32 cols x 128 rows each) — no LDS/STG on the LSU for the output.
// ---------------------------------------------------------------------------
static constexpr int KC = 64;
static constexpr int OFF_SB  = 0;
static constexpr int OFF_SP  = 512;
static constexpr int OFF_BUF = 1024;
static constexpr int SLAB    = 16384;      // one 128x64 fp16 operand slab
static constexpr int STAGE   = 2 * SLAB;   // 32 KB
static constexpr int SMEM_TOTAL = OFF_BUF + 2 * STAGE;  // 66560 B
static constexpr int EPI_REGION = 16384;   // 32 cols x 128 rows f32, SW128

__device__ __forceinline__ void load_slab(uint32_t dst, const __half* __restrict__ g,
                                          int row0, int kk, int tid) {
    #pragma unroll
    for (int l = 0; l < 4; l++) {
        const int cidx = tid + l * 256;     // 0..1023
        const int row  = cidx >> 3;
        const int ch   = cidx & 7;
        const uint32_t off = (uint32_t)(row * 128 + ((ch ^ (row & 7)) << 4));
        cp_async16(dst + off, g + (size_t)(row0 + row) * H_ + kk + ch * 8);
    }
}

__device__ __forceinline__ void load_stage(uint32_t buf, size_t base, int i0, int j0,
                                           int kk, int tid) {
    load_slab(buf,        g_Ah + base, i0, kk, tid);
    load_slab(buf + SLAB, g_Ph + base, j0, kk, tid);
}

// SW128 swizzle for 128B-pitch rows
__device__ __forceinline__ uint32_t sw128(uint32_t byte_off) {
    return byte_off ^ ((byte_off >> 3) & 0x70u);
}

__global__ void __launch_bounds__(256, 3)
gemm_kernel(float* __restrict__ out, const __grid_constant__ CUtensorMap tmap) {
    extern __shared__ char smem[];
    const uint32_t sbase = smem_u32(smem);
    const int tid  = threadIdx.x;
    const int lane = tid & 31;
    const int warp = tid >> 5;
    const int m_base = (warp & 1) * 64;   // 2 warps over M
    const int n_base = (warp >> 1) * 32;  // 4 warps over N

    const int b  = blockIdx.z;
    const int i0 = blockIdx.y * 128;
    const int j0 = blockIdx.x * 128;
    const size_t base = (size_t)b * L_ * H_;

    // prologue: both K-chunks in flight immediately
    load_stage(sbase + OFF_BUF,         base, i0, j0, 0,  tid); CP_COMMIT();
    load_stage(sbase + OFF_BUF + STAGE, base, i0, j0, KC, tid); CP_COMMIT();

    // rank-1 vector slices
    if (tid < 128)       ((float*)(smem + OFF_SB))[tid]       = g_sbody[b * L_ + i0 + tid];
    else                 ((float*)(smem + OFF_SP))[tid - 128] = g_spun [b * L_ + j0 + (tid - 128)];

    float acc[4][4][4];
    #pragma unroll
    for (int mi = 0; mi < 4; mi++)
        #pragma unroll
        for (int ni = 0; ni < 4; ni++)
            #pragma unroll
            for (int k = 0; k < 4; k++) acc[mi][ni][k] = 0.f;

    const int a_row  = (lane & 7) + ((lane >> 3) & 1) * 8;
    const int a_half = lane >> 4;
    const int b_row  = (lane & 7) + (lane >> 4) * 8;
    const int b_half = (lane >> 3) & 1;

    #pragma unroll
    for (int c = 0; c < 2; c++) {
        if (c == 0) CP_WAIT(1); else CP_WAIT(0);
        __syncthreads();

        const uint32_t buf = sbase + OFF_BUF + c * STAGE;
        #pragma unroll
        for (int ks = 0; ks < KC / 16; ks++) {
            uint32_t bH[4][2];
            {
                const int chunk = ks * 2 + b_half;
                #pragma unroll
                for (int np = 0; np < 2; np++) {
                    const int nrow = n_base + np * 16 + b_row;
                    const uint32_t off = (uint32_t)(nrow * 128 + ((chunk ^ (nrow & 7)) << 4));
                    uint32_t r[4];
                    ldsm_x4(r, buf + SLAB + off);          // Ph
                    bH[np*2][0] = r[0]; bH[np*2][1] = r[1];
                    bH[np*2+1][0] = r[2]; bH[np*2+1][1] = r[3];
                }
            }
            const int achunk = ks * 2 + a_half;
            #pragma unroll
            for (int mi = 0; mi < 4; mi++) {
                uint32_t aH[4];
                const int arow = m_base + mi * 16 + a_row;
                const uint32_t off = (uint32_t)(arow * 128 + ((achunk ^ (arow & 7)) << 4));
                ldsm_x4(aH, buf + off);                    // Ah
                #pragma unroll
                for (int ni = 0; ni < 4; ni++)
                    mma_f16(acc[mi][ni], aH, bH[ni]);
            }
        }
    }

    // --- epilogue: add rank-1 vectors, stage into 4 SW128 regions, TMA store ---
    const float* sbV = (const float*)(smem + OFF_SB);
    const float* spV = (const float*)(smem + OFF_SP);
    const int r4 = lane >> 2;
    const int c2 = (lane & 3) << 1;

    __syncthreads();   // all warps done reading operand smem before overwrite
    // region = warp's n-block (32 cols); two warps (m halves) share a region
    char* ereg = smem + OFF_BUF + (warp >> 1) * EPI_REGION;

    #pragma unroll
    for (int mi = 0; mi < 4; mi++) {
        const int r0 = m_base + mi * 16 + r4;   // CTA-local row 0..127
        const float sb0 = sbV[r0];
        const float sb1 = sbV[r0 + 8];
        #pragma unroll
        for (int ni = 0; ni < 4; ni++) {
            const int colL = ni * 8 + c2;        // 0..30 within region
            const float sp0 = spV[n_base + colL];
            const float sp1 = spV[n_base + colL + 1];
            float2 v0 = make_float2(acc[mi][ni][0] + sb0 + sp0,
                                    acc[mi][ni][1] + sb0 + sp1);
            float2 v1 = make_float2(acc[mi][ni][2] + sb1 + sp0,
                                    acc[mi][ni][3] + sb1 + sp1);
            *reinterpret_cast<float2*>(ereg + sw128((uint32_t)(r0 * 128 + colL * 4)))       = v0;
            *reinterpret_cast<float2*>(ereg + sw128((uint32_t)((r0 + 8) * 128 + colL * 4))) = v1;
        }
    }
    __syncthreads();   // all regions fully staged

    if (tid < 4) {
        asm volatile("fence.proxy.async.shared::cta;" ::: "memory");
        const int x = j0 + tid * 32;            // column (dim0, elements)
        const int y = b * L_ + i0;              // row (dim1)
        const uint32_t sa = sbase + OFF_BUF + tid * EPI_REGION;
        asm volatile(
            "cp.async.bulk.tensor.2d.global.shared::cta.tile.bulk_group "
            "[%0, {%1, %2}], [%3];"
            :: "l"(&tmap), "r"(x), "r"(y), "r"(sa) : "memory");
        asm volatile("cp.async.bulk.commit_group;" ::: "memory");
        asm volatile("cp.async.bulk.wait_group 0;" ::: "memory");
    }
}

// ---------------------------------------------------------------------------
// Launch
// ---------------------------------------------------------------------------
typedef CUresult (*EncFn)(CUtensorMap*, CUtensorMapDataType, cuuint32_t, void*,
                          const cuuint64_t*, const cuuint64_t*, const cuuint32_t*,
                          const cuuint32_t*, CUtensorMapInterleave, CUtensorMapSwizzle,
                          CUtensorMapL2promotion, CUtensorMapFloatOOBfill);

extern "C" void kernel_launch(void* const* d_in, const int* in_sizes, int n_in,
                              void* d_out, int out_size) {
    const float* body = (const float*)d_in[n_in - 3];
    const float* pun  = (const float*)d_in[n_in - 2];
    const float* w_u  = (const float*)d_in[n_in - 1];
    float* out = (float*)d_out;

    static CUtensorMap h_tmap;
    static bool init_done = false;
    if (!init_done) {
        void* fp = nullptr;
        cudaDriverEntryPointQueryResult qr;
        cudaGetDriverEntryPointByVersion("cuTensorMapEncodeTiled", &fp, 12000,
                                         cudaEnableDefault, &qr);
        // out viewed as 2D [B_*L_, L_] f32; box 32x128, SW128 (box0*4B = 128B limit)
        cuuint64_t dims[2]    = {L_, (cuuint64_t)B_ * L_};
        cuuint64_t strides[1] = {L_ * sizeof(float)};
        cuuint32_t box[2]     = {32, 128};
        cuuint32_t es[2]      = {1, 1};
        ((EncFn)fp)(&h_tmap, CU_TENSOR_MAP_DATA_TYPE_FLOAT32, 2, d_out,
                    dims, strides, box, es,
                    CU_TENSOR_MAP_INTERLEAVE_NONE, CU_TENSOR_MAP_SWIZZLE_128B,
                    CU_TENSOR_MAP_L2_PROMOTION_L2_128B,
                    CU_TENSOR_MAP_FLOAT_OOB_FILL_NONE);
        cudaFuncSetAttribute(gemm_kernel, cudaFuncAttributeMaxDynamicSharedMemorySize,
                             SMEM_TOTAL);
        init_done = true;
    }

    prep_kernel<<<(B_ * L_) / 8, 256>>>(body, pun, w_u);
    gemm_kernel<<<dim3(8, 8, B_), 256, SMEM_TOTAL>>>(out, h_tmap);
}

// round 9
// speedup vs baseline: 1.5615x; 1.1059x over previous
#include <cuda_runtime.h>
#include <cuda_fp16.h>
#include <cuda.h>
#include <cstdint>

// Problem constants
#define B_  64
#define L_  1024
#define H_  128

// ---------------------------------------------------------------------------
// Scratch (allocation-free rule: __device__ globals)
// fp16 1-term scheme: ah = fp16(body*w3); ph = fp16(pun); s_cross ≈ ah·ph
// (measured rel_err 1.75e-4, deterministic inputs)
// ---------------------------------------------------------------------------
__device__ __align__(16) __half g_Ah[(size_t)B_*L_*H_];
__device__ __align__(16) __half g_Ph[(size_t)B_*L_*H_];
__device__ float g_sbody[B_*L_];
__device__ float g_spun [B_*L_];

// ---------------------------------------------------------------------------
// Helpers (base-arch only: NO tcgen05 — ptxas target is sm_103, not sm_103a.
// cp.async.bulk.tensor IS base sm_90+.)
// ---------------------------------------------------------------------------
__device__ __forceinline__ uint32_t smem_u32(const void* p) {
    uint32_t a;
    asm("{ .reg .u64 t; cvta.to.shared.u64 t, %1; cvt.u32.u64 %0, t; }" : "=r"(a) : "l"(p));
    return a;
}

__device__ __forceinline__ void ldsm_x4(uint32_t* r, uint32_t addr) {
    asm volatile("ldmatrix.sync.aligned.m8n8.x4.shared.b16 {%0,%1,%2,%3}, [%4];"
        : "=r"(r[0]), "=r"(r[1]), "=r"(r[2]), "=r"(r[3]) : "r"(addr));
}

// D += A * B  (m16n8k16, fp16 in, f32 accum)
__device__ __forceinline__ void mma_f16(float* d, const uint32_t* a, const uint32_t* b) {
    asm volatile(
        "mma.sync.aligned.m16n8k16.row.col.f32.f16.f16.f32 "
        "{%0,%1,%2,%3}, {%4,%5,%6,%7}, {%8,%9}, {%0,%1,%2,%3};"
        : "+f"(d[0]), "+f"(d[1]), "+f"(d[2]), "+f"(d[3])
        : "r"(a[0]), "r"(a[1]), "r"(a[2]), "r"(a[3]), "r"(b[0]), "r"(b[1]));
}

__device__ __forceinline__ void cp_async16(uint32_t dst, const void* src) {
    asm volatile("cp.async.cg.shared.global [%0], [%1], 16;" :: "r"(dst), "l"(src));
}
#define CP_COMMIT() asm volatile("cp.async.commit_group;" ::: "memory")
#define CP_WAIT(n)  asm volatile("cp.async.wait_group %0;" :: "n"(n) : "memory")

// SW128 swizzle for 128B-pitch rows (epilogue staging / TMA)
__device__ __forceinline__ uint32_t sw128(uint32_t byte_off) {
    return byte_off ^ ((byte_off >> 3) & 0x70u);
}

// ---------------------------------------------------------------------------
// Kernel 1: preprocess — ah = fp16(body*w3); ph = fp16(pun); rank-1 dots.
// ---------------------------------------------------------------------------
__device__ __forceinline__ uint32_t pack_h2(float x, float y) {
    __half2 v(__float2half(x), __float2half(y));
    return *reinterpret_cast<uint32_t*>(&v);
}

__global__ void __launch_bounds__(256) prep_kernel(const float* __restrict__ body,
                                                   const float* __restrict__ pun,
                                                   const float* __restrict__ w_u) {
    const int warp = threadIdx.x >> 5, lane = threadIdx.x & 31;
    const int r = blockIdx.x * 8 + warp;
    const int d4 = lane * 4;

    const float4 w1 = *reinterpret_cast<const float4*>(w_u + d4);
    const float4 w2 = *reinterpret_cast<const float4*>(w_u + H_ + d4);
    const float4 w3 = *reinterpret_cast<const float4*>(w_u + 2 * H_ + d4);

    const size_t idx = (size_t)r * H_ + d4;
    const float4 bv = *reinterpret_cast<const float4*>(body + idx);
    const float4 pv = *reinterpret_cast<const float4*>(pun + idx);

    float a0 = bv.x * w3.x, a1 = bv.y * w3.y, a2 = bv.z * w3.z, a3 = bv.w * w3.w;
    *reinterpret_cast<uint2*>(g_Ah + idx) =
        make_uint2(pack_h2(a0, a1), pack_h2(a2, a3));
    *reinterpret_cast<uint2*>(g_Ph + idx) =
        make_uint2(pack_h2(pv.x, pv.y), pack_h2(pv.z, pv.w));

    float sb = bv.x * w1.x + bv.y * w1.y + bv.z * w1.z + bv.w * w1.w;
    float sp = pv.x * w2.x + pv.y * w2.y + pv.z * w2.z + pv.w * w2.w;
    #pragma unroll
    for (int o = 16; o > 0; o >>= 1) {
        sb += __shfl_down_sync(0xFFFFFFFFu, sb, o);
        sp += __shfl_down_sync(0xFFFFFFFFu, sp, o);
    }
    if (lane == 0) { g_sbody[r] = sb; g_spun[r] = sp; }
}

// ---------------------------------------------------------------------------
// Kernel 2: fused-j batched GEMM.
//   CTA = (i-block, batch); loops over all 8 j-blocks.
//   A (Ah) tile resident in smem for the whole CTA; P (Ph) double-buffered.
//   4 warps, 2x2 warp grid, 64x64 warp tiles.
//   Epilogue per j: stage into the DEAD P buffer (2x16KB sub-buffers),
//   pipelined TMA 2D tensor stores (32 cols x 128 rows, SW128).
// Slab format (A and P): 128 rows x 256B (128 fp16); 16B chunk swizzle
//   phys = row*256 + ((ch ^ (row&7))<<4)
// ---------------------------------------------------------------------------
static constexpr int OFF_SB = 0;        // 128 f32 sbody slice
static constexpr int OFF_SP = 512;      // 1024 f32 spun (full row)
static constexpr int OFF_A  = 5120;     // 32 KB A slab
static constexpr int OFF_P0 = 37888;    // 32 KB P slab 0
static constexpr int OFF_P1 = 70656;    // 32 KB P slab 1
static constexpr int SMEM_TOTAL = 103424;   // -> occupancy 2

__device__ __forceinline__ void load_slab128(uint32_t dst, const __half* __restrict__ g,
                                             int row0, int tid) {
    #pragma unroll
    for (int l = 0; l < 16; l++) {
        const int cidx = tid + l * 128;     // 0..2047 16B chunks
        const int row  = cidx >> 4;
        const int ch   = cidx & 15;
        const uint32_t off = (uint32_t)(row * 256 + ((ch ^ (row & 7)) << 4));
        cp_async16(dst + off, g + (size_t)(row0 + row) * H_ + ch * 8);
    }
}

__global__ void __launch_bounds__(128, 2)
gemm_kernel(float* __restrict__ out, const __grid_constant__ CUtensorMap tmap) {
    extern __shared__ char smem[];
    const uint32_t sbase = smem_u32(smem);
    const int tid  = threadIdx.x;
    const int lane = tid & 31;
    const int warp = tid >> 5;
    const int wm = warp & 1;            // 2 warps over M
    const int wn = warp >> 1;           // 2 warps over N
    const int m_base = wm * 64, n_base = wn * 64;

    const int i0 = blockIdx.x * 128;
    const int b  = blockIdx.y;
    const size_t base = (size_t)b * L_ * H_;

    // prologue: A tile + first P tile in flight
    load_slab128(sbase + OFF_A,  g_Ah + base, i0, tid);
    load_slab128(sbase + OFF_P0, g_Ph + base, 0,  tid);
    CP_COMMIT();

    // rank-1 vectors: sbody slice (128) + full spun row (1024)
    ((float*)(smem + OFF_SB))[tid] = g_sbody[b * L_ + i0 + tid];
    #pragma unroll
    for (int l = 0; l < 8; l++)
        ((float*)(smem + OFF_SP))[tid + l * 128] = g_spun[b * L_ + tid + l * 128];

    // fragment addressing (constant per thread)
    const int a_row  = (lane & 7) + ((lane >> 3) & 1) * 8;
    const int a_half = lane >> 4;
    const int b_row  = (lane & 7) + (lane >> 4) * 8;
    const int b_half = (lane >> 3) & 1;

    const float* sbV = (const float*)(smem + OFF_SB);
    const float* spV = (const float*)(smem + OFF_SP);
    const int r4 = lane >> 2;
    const int c2 = (lane & 3) << 1;

    #pragma unroll 1
    for (int j = 0; j < 8; j++) {
        const uint32_t pbuf = sbase + ((j & 1) ? OFF_P1 : OFF_P0);

        // prefetch next P into the buffer freed by last iteration's epilogue
        if (j < 7) {
            load_slab128(sbase + ((j & 1) ? OFF_P0 : OFF_P1), g_Ph + base,
                         (j + 1) * 128, tid);
            CP_COMMIT();
            CP_WAIT(1);
        } else {
            CP_WAIT(0);
        }
        __syncthreads();   // P(j) visible; previous epilogue fully drained

        float acc[4][8][4];
        #pragma unroll
        for (int mi = 0; mi < 4; mi++)
            #pragma unroll
            for (int ni = 0; ni < 8; ni++)
                #pragma unroll
                for (int k = 0; k < 4; k++) acc[mi][ni][k] = 0.f;

        #pragma unroll
        for (int ks = 0; ks < 8; ks++) {
            uint32_t bH[8][2];
            #pragma unroll
            for (int np = 0; np < 4; np++) {
                const int nrow = n_base + np * 16 + b_row;
                const uint32_t off = (uint32_t)(nrow * 256
                    + (((ks * 2 + b_half) ^ (nrow & 7)) << 4));
                uint32_t r[4];
                ldsm_x4(r, pbuf + off);
                bH[np*2][0] = r[0]; bH[np*2][1] = r[1];
                bH[np*2+1][0] = r[2]; bH[np*2+1][1] = r[3];
            }
            #pragma unroll
            for (int mi = 0; mi < 4; mi++) {
                uint32_t aH[4];
                const int arow = m_base + mi * 16 + a_row;
                const uint32_t off = (uint32_t)(arow * 256
                    + (((ks * 2 + a_half) ^ (arow & 7)) << 4));
                ldsm_x4(aH, sbase + OFF_A + off);
                #pragma unroll
                for (int ni = 0; ni < 8; ni++)
                    mma_f16(acc[mi][ni], aH, bH[ni]);
            }
        }
        __syncthreads();   // all warps done reading pbuf -> reuse as staging

        // --- epilogue: 4 regions of 32 cols, pipelined through 2 sub-buffers ---
        const int j0 = j * 128;
        #pragma unroll
        for (int r = 0; r < 4; r++) {
            if (r >= 2) {   // sub-buffer r&1 reused: its TMA (r-2) must be done
                if (tid == 0)
                    asm volatile("cp.async.bulk.wait_group 1;" ::: "memory");
                __syncthreads();
            }
            if (wn == (r >> 1)) {
                char* sub = smem + (pbuf - sbase) + (r & 1) * 16384;
                #pragma unroll
                for (int mi = 0; mi < 4; mi++) {
                    const int row = m_base + mi * 16 + r4;
                    const float sb0 = sbV[row];
                    const float sb1 = sbV[row + 8];
                    #pragma unroll
                    for (int nq = 0; nq < 4; nq++) {
                        const int ni = (r & 1) * 4 + nq;
                        const int colG = n_base + ni * 8 + c2;   // tile col
                        const int colR = nq * 8 + c2;            // region col
                        const float sp0 = spV[j0 + colG];
                        const float sp1 = spV[j0 + colG + 1];
                        float2 v0 = make_float2(acc[mi][ni][0] + sb0 + sp0,
                                                acc[mi][ni][1] + sb0 + sp1);
                        float2 v1 = make_float2(acc[mi][ni][2] + sb1 + sp0,
                                                acc[mi][ni][3] + sb1 + sp1);
                        *reinterpret_cast<float2*>(sub + sw128((uint32_t)(row * 128 + colR * 4)))       = v0;
                        *reinterpret_cast<float2*>(sub + sw128((uint32_t)((row + 8) * 128 + colR * 4))) = v1;
                    }
                }
            }
            __syncthreads();   // region staged
            if (tid == 0) {
                asm volatile("fence.proxy.async.shared::cta;" ::: "memory");
                const int x = j0 + r * 32;
                const int y = b * L_ + i0;
                const uint32_t sa = pbuf + (r & 1) * 16384;
                asm volatile(
                    "cp.async.bulk.tensor.2d.global.shared::cta.tile.bulk_group "
                    "[%0, {%1, %2}], [%3];"
                    :: "l"(&tmap), "r"(x), "r"(y), "r"(sa) : "memory");
                asm volatile("cp.async.bulk.commit_group;" ::: "memory");
            }
        }
        if (tid == 0)
            asm volatile("cp.async.bulk.wait_group 0;" ::: "memory");
        __syncthreads();   // pbuf fully drained before next-next prefetch
    }
}

// ---------------------------------------------------------------------------
// Launch
// ---------------------------------------------------------------------------
typedef CUresult (*EncFn)(CUtensorMap*, CUtensorMapDataType, cuuint32_t, void*,
                          const cuuint64_t*, const cuuint64_t*, const cuuint32_t*,
                          const cuuint32_t*, CUtensorMapInterleave, CUtensorMapSwizzle,
                          CUtensorMapL2promotion, CUtensorMapFloatOOBfill);

extern "C" void kernel_launch(void* const* d_in, const int* in_sizes, int n_in,
                              void* d_out, int out_size) {
    const float* body = (const float*)d_in[n_in - 3];
    const float* pun  = (const float*)d_in[n_in - 2];
    const float* w_u  = (const float*)d_in[n_in - 1];
    float* out = (float*)d_out;

    static CUtensorMap h_tmap;
    static bool init_done = false;
    if (!init_done) {
        void* fp = nullptr;
        cudaDriverEntryPointQueryResult qr;
        cudaGetDriverEntryPointByVersion("cuTensorMapEncodeTiled", &fp, 12000,
                                         cudaEnableDefault, &qr);
        // out viewed as 2D [B_*L_, L_] f32; box 32x128, SW128 (box0*4B = 128B limit)
        cuuint64_t dims[2]    = {L_, (cuuint64_t)B_ * L_};
        cuuint64_t strides[1] = {L_ * sizeof(float)};
        cuuint32_t box[2]     = {32, 128};
        cuuint32_t es[2]      = {1, 1};
        ((EncFn)fp)(&h_tmap, CU_TENSOR_MAP_DATA_TYPE_FLOAT32, 2, d_out,
                    dims, strides, box, es,
                    CU_TENSOR_MAP_INTERLEAVE_NONE, CU_TENSOR_MAP_SWIZZLE_128B,
                    CU_TENSOR_MAP_L2_PROMOTION_L2_128B,
                    CU_TENSOR_MAP_FLOAT_OOB_FILL_NONE);
        cudaFuncSetAttribute(gemm_kernel, cudaFuncAttributeMaxDynamicSharedMemorySize,
                             SMEM_TOTAL);
        init_done = true;
    }

    prep_kernel<<<(B_ * L_) / 8, 256>>>(body, pun, w_u);
    gemm_kernel<<<dim3(8, B_), 128, SMEM_TOTAL>>>(out, h_tmap);
}